// round 1
// baseline (speedup 1.0000x reference)
#include <cuda_runtime.h>
#include <math.h>

// Scratch: per-image softmax probabilities (max 1024 batches * 16 digits * 10)
__device__ float g_probs[1024 * 16 * 10];

// ---------------------------------------------------------------------------
// Kernel 1: fused LeNet forward + softmax. One CTA of 256 threads per image.
// ---------------------------------------------------------------------------
__global__ void __launch_bounds__(256, 4) cnn_kernel(
    const float* __restrict__ inputs,
    const float* __restrict__ cw1, const float* __restrict__ cb1,
    const float* __restrict__ cw2, const float* __restrict__ cb2,
    const float* __restrict__ dw1, const float* __restrict__ db1,
    const float* __restrict__ dw2, const float* __restrict__ db2,
    const float* __restrict__ dw3, const float* __restrict__ db3)
{
    __shared__ float  s_img[28 * 28];          // 784
    __shared__ float  s_w1[150];               // 5*5*1*6
    __shared__ float4 s_w2[600];               // 5*5*6*16 / 4
    __shared__ float  s_b1[6];
    __shared__ float  s_b2[16];
    __shared__ float  s_c1[24 * 24 * 6];       // 3456
    __shared__ float  s_p1[12 * 12 * 6];       // 864
    __shared__ float  s_c2[8 * 8 * 16];        // 1024
    __shared__ float  s_p2[256];
    __shared__ float  s_fc1[120];
    __shared__ float  s_fc2[84];
    __shared__ float  s_logits[10];

    const int img = blockIdx.x;
    const int t   = threadIdx.x;

    // ---- stage loads ----
    const float* im = inputs + (size_t)img * 784;
    for (int i = t; i < 784; i += 256) s_img[i] = im[i];
    for (int i = t; i < 150; i += 256) s_w1[i] = cw1[i];
    {
        const float4* w2v = reinterpret_cast<const float4*>(cw2);
        for (int i = t; i < 600; i += 256) s_w2[i] = w2v[i];
    }
    if (t < 6)  s_b1[t] = cb1[t];
    if (t < 16) s_b2[t] = cb2[t];
    __syncthreads();

    // ---- conv1: 24x24x6, 5x5 valid, relu ----
    for (int idx = t; idx < 3456; idx += 256) {
        int c  = idx % 6;
        int xy = idx / 6;
        int x  = xy % 24;
        int y  = xy / 24;
        float acc = s_b1[c];
        const float* ip = s_img + y * 28 + x;
        #pragma unroll
        for (int ky = 0; ky < 5; ky++) {
            #pragma unroll
            for (int kx = 0; kx < 5; kx++) {
                acc = fmaf(ip[ky * 28 + kx], s_w1[(ky * 5 + kx) * 6 + c], acc);
            }
        }
        s_c1[idx] = fmaxf(acc, 0.0f);
    }
    __syncthreads();

    // ---- maxpool 2x2 -> 12x12x6 ----
    for (int idx = t; idx < 864; idx += 256) {
        int c  = idx % 6;
        int xy = idx / 6;
        int x  = xy % 12;
        int y  = xy / 12;
        int b0 = ((2 * y) * 24 + 2 * x) * 6 + c;
        float m = fmaxf(fmaxf(s_c1[b0], s_c1[b0 + 6]),
                        fmaxf(s_c1[b0 + 24 * 6], s_c1[b0 + 24 * 6 + 6]));
        s_p1[idx] = m;
    }
    __syncthreads();

    // ---- conv2: 8x8x16, 5x5x6 valid, relu ----
    {
        int pos = t & 63;          // spatial position 0..63
        int g   = t >> 6;          // channel group 0..3 (4 channels each)
        int x   = pos & 7;
        int y   = pos >> 3;
        float a0 = s_b2[g * 4 + 0];
        float a1 = s_b2[g * 4 + 1];
        float a2 = s_b2[g * 4 + 2];
        float a3 = s_b2[g * 4 + 3];
        #pragma unroll
        for (int ky = 0; ky < 5; ky++) {
            #pragma unroll
            for (int kx = 0; kx < 5; kx++) {
                const float* pp = s_p1 + ((y + ky) * 12 + (x + kx)) * 6;
                const int wb = ((ky * 5 + kx) * 6) * 4 + g;
                #pragma unroll
                for (int i = 0; i < 6; i++) {
                    float  p = pp[i];
                    float4 w = s_w2[wb + i * 4];
                    a0 = fmaf(p, w.x, a0);
                    a1 = fmaf(p, w.y, a1);
                    a2 = fmaf(p, w.z, a2);
                    a3 = fmaf(p, w.w, a3);
                }
            }
        }
        int ob = (y * 8 + x) * 16 + g * 4;
        s_c2[ob + 0] = fmaxf(a0, 0.0f);
        s_c2[ob + 1] = fmaxf(a1, 0.0f);
        s_c2[ob + 2] = fmaxf(a2, 0.0f);
        s_c2[ob + 3] = fmaxf(a3, 0.0f);
    }
    __syncthreads();

    // ---- maxpool 2x2 -> 4x4x16 (flattened NHWC order) ----
    {
        int idx = t;
        if (idx < 256) {
            int c  = idx % 16;
            int xy = idx / 16;
            int x  = xy % 4;
            int y  = xy / 4;
            int b0 = ((2 * y) * 8 + 2 * x) * 16 + c;
            float m = fmaxf(fmaxf(s_c2[b0], s_c2[b0 + 16]),
                            fmaxf(s_c2[b0 + 8 * 16], s_c2[b0 + 8 * 16 + 16]));
            s_p2[idx] = m;
        }
    }
    __syncthreads();

    // ---- fc1: 256 -> 120, relu ----
    if (t < 120) {
        float acc = db1[t];
        #pragma unroll 8
        for (int k = 0; k < 256; k++) {
            acc = fmaf(s_p2[k], __ldg(&dw1[k * 120 + t]), acc);
        }
        s_fc1[t] = fmaxf(acc, 0.0f);
    }
    __syncthreads();

    // ---- fc2: 120 -> 84, relu ----
    if (t < 84) {
        float acc = db2[t];
        #pragma unroll 8
        for (int k = 0; k < 120; k++) {
            acc = fmaf(s_fc1[k], __ldg(&dw2[k * 84 + t]), acc);
        }
        s_fc2[t] = fmaxf(acc, 0.0f);
    }
    __syncthreads();

    // ---- fc3: 84 -> 10 ----
    if (t < 10) {
        float acc = db3[t];
        #pragma unroll
        for (int k = 0; k < 84; k++) {
            acc = fmaf(s_fc2[k], __ldg(&dw3[k * 10 + t]), acc);
        }
        s_logits[t] = acc;
    }
    __syncthreads();

    // ---- softmax, write to scratch ----
    if (t == 0) {
        float mx = s_logits[0];
        #pragma unroll
        for (int j = 1; j < 10; j++) mx = fmaxf(mx, s_logits[j]);
        float e[10];
        float sum = 0.0f;
        #pragma unroll
        for (int j = 0; j < 10; j++) { e[j] = expf(s_logits[j] - mx); sum += e[j]; }
        float inv = 1.0f / sum;
        float* po = g_probs + (size_t)img * 10;
        #pragma unroll
        for (int j = 0; j < 10; j++) po[j] = e[j] * inv;
    }
}

// ---------------------------------------------------------------------------
// Kernel 2: Luhn DP. One thread per batch element.
// conv_pmf followed by mod10 == circular convolution mod 10.
// ---------------------------------------------------------------------------
__global__ void luhn_kernel(float* __restrict__ out, int B, int n)
{
    int b = blockIdx.x * blockDim.x + threadIdx.x;
    if (b >= B) return;

    const int LUHN[10] = {0, 5, 1, 6, 2, 7, 3, 8, 4, 9};
    const float* p = g_probs + (size_t)b * n * 10;
    const int m = n - 1;  // number of non-check digits

    float cur[10];
    // i = 0: conv of delta(0) with digit-1 pmf (possibly permuted)
    {
        const float* d = p + 10;
        bool perm = ((0 & 1) == (m & 1));
        #pragma unroll
        for (int j = 0; j < 10; j++) cur[j] = perm ? d[LUHN[j]] : d[j];
    }
    for (int i = 1; i < m; i++) {
        const float* d = p + (size_t)(i + 1) * 10;
        bool perm = ((i & 1) == (m & 1));
        float dd[10];
        #pragma unroll
        for (int j = 0; j < 10; j++) dd[j] = perm ? d[LUHN[j]] : d[j];

        float nxt[10];
        #pragma unroll
        for (int s = 0; s < 10; s++) nxt[s] = 0.0f;
        #pragma unroll
        for (int a = 0; a < 10; a++) {
            #pragma unroll
            for (int q = 0; q < 10; q++) {
                nxt[(a + q) % 10] = fmaf(cur[a], dd[q], nxt[(a + q) % 10]);
            }
        }
        #pragma unroll
        for (int s = 0; s < 10; s++) cur[s] = nxt[s];
    }

    // total[10] = sum_{a=1..9} check_digit[a] * cur[10-a]
    const float* cd = p;
    float t10 = 0.0f;
    #pragma unroll
    for (int a = 1; a < 10; a++) t10 = fmaf(cd[a], cur[10 - a], t10);
    out[b] = logf(t10);
}

// ---------------------------------------------------------------------------
extern "C" void kernel_launch(void* const* d_in, const int* in_sizes, int n_in,
                              void* d_out, int out_size)
{
    const float* inputs = (const float*)d_in[0];
    const float* cw1    = (const float*)d_in[1];
    const float* cb1    = (const float*)d_in[2];
    const float* cw2    = (const float*)d_in[3];
    const float* cb2    = (const float*)d_in[4];
    const float* dw1    = (const float*)d_in[5];
    const float* db1    = (const float*)d_in[6];
    const float* dw2    = (const float*)d_in[7];
    const float* db2    = (const float*)d_in[8];
    const float* dw3    = (const float*)d_in[9];
    const float* db3    = (const float*)d_in[10];
    float* out = (float*)d_out;

    const int B = out_size;                      // 1024 batches
    const int n = in_sizes[0] / (B * 784);       // 16 digits
    const int nimg = B * n;

    cnn_kernel<<<nimg, 256>>>(inputs, cw1, cb1, cw2, cb2,
                              dw1, db1, dw2, db2, dw3, db3);
    luhn_kernel<<<(B + 127) / 128, 128>>>(out, B, n);
}

// round 2
// speedup vs baseline: 2.1790x; 2.1790x over previous
#include <cuda_runtime.h>
#include <math.h>

typedef unsigned long long ull;

// ---------------------------------------------------------------------------
// packed fp32x2 helpers (Blackwell FFMA2)
// ---------------------------------------------------------------------------
#define FMA2(d, a, b, c) \
    asm("fma.rn.f32x2 %0, %1, %2, %3;" : "=l"(d) : "l"(a), "l"(b), "l"(c))

static __device__ __forceinline__ ull pack2(float lo, float hi) {
    ull r; asm("mov.b64 %0, {%1, %2};" : "=l"(r) : "f"(lo), "f"(hi)); return r;
}
static __device__ __forceinline__ float2 unpack2(ull v) {
    float2 r; asm("mov.b64 {%0, %1}, %2;" : "=f"(r.x), "=f"(r.y) : "l"(v)); return r;
}
static __device__ __forceinline__ ull lds64(const float* p) {
    return *reinterpret_cast<const ull*>(p);
}

// Scratch: per-image softmax probabilities (1024 batches * 16 digits * 10)
__device__ float g_probs[1024 * 16 * 10];

// ---------------------------------------------------------------------------
// shared memory layout (float offsets)
// ---------------------------------------------------------------------------
#define OFF_DW1T  0        // [120][258]  (padded, transposed dw1)
#define DW1_STR   258
#define OFF_DW2T  30960    // [84][122]   (padded, transposed dw2)
#define DW2_STR   122
#define OFF_DW3   41208    // [84*10]
#define OFF_W1    42048    // [25][6]
#define OFF_W2    42200    // [150][16]
#define OFF_B1    44600    // 6
#define OFF_B2    44608    // 16
#define OFF_DB1   44624    // 120
#define OFF_DB2   44744    // 84
#define OFF_DB3   44828    // 10
#define OFF_Q     44840    // per-quarter blocks
#define Q_STRIDE  2128
// within a quarter:
#define Q_IMG     0        // 784
#define Q_P1T     784      // [6][144]  (channel-major pooled conv1)
#define Q_P2      1648     // 256 (NHWC flat 4*4*16)
#define Q_FC1     1904     // 120
#define Q_FC2     2024     // 84
#define Q_LOG     2108     // 10
#define SMEM_FLOATS (OFF_Q + 4 * Q_STRIDE)   // 53352 floats = 213408 B

#define QBAR() asm volatile("bar.sync %0, 128;" :: "r"(q + 1) : "memory")

// ---------------------------------------------------------------------------
// Kernel 1: persistent fused LeNet. 148 CTAs x 512 threads, 4 images in
// flight per CTA (128-thread quarters, named barriers).
// ---------------------------------------------------------------------------
__global__ void __launch_bounds__(512, 1) cnn_kernel(
    const float* __restrict__ inputs,
    const float* __restrict__ cw1, const float* __restrict__ cb1,
    const float* __restrict__ cw2, const float* __restrict__ cb2,
    const float* __restrict__ dw1, const float* __restrict__ db1,
    const float* __restrict__ dw2, const float* __restrict__ db2,
    const float* __restrict__ dw3, const float* __restrict__ db3,
    int nimg)
{
    extern __shared__ float sm[];
    const int tid = threadIdx.x;

    // ---- one-time weight staging (coalesced reads, scattered smem writes) ----
    for (int idx = tid; idx < 256 * 120; idx += 512) {
        int k = idx / 120, j = idx % 120;               // dw1[k][j]
        sm[OFF_DW1T + j * DW1_STR + k] = dw1[idx];
    }
    for (int idx = tid; idx < 120 * 84; idx += 512) {
        int k = idx / 84, j = idx % 84;                 // dw2[k][j]
        sm[OFF_DW2T + j * DW2_STR + k] = dw2[idx];
    }
    for (int idx = tid; idx < 840;  idx += 512) sm[OFF_DW3 + idx] = dw3[idx];
    for (int idx = tid; idx < 150;  idx += 512) sm[OFF_W1  + idx] = cw1[idx];
    for (int idx = tid; idx < 2400; idx += 512) sm[OFF_W2  + idx] = cw2[idx];
    if (tid < 6)   sm[OFF_B1  + tid] = cb1[tid];
    if (tid < 16)  sm[OFF_B2  + tid] = cb2[tid];
    if (tid < 120) sm[OFF_DB1 + tid] = db1[tid];
    if (tid < 84)  sm[OFF_DB2 + tid] = db2[tid];
    if (tid < 10)  sm[OFF_DB3 + tid] = db3[tid];
    __syncthreads();

    const int q  = tid >> 7;          // quarter 0..3
    const int t  = tid & 127;         // thread within quarter
    const int rt = (t + (q << 5)) & 127;  // rotated role index (SMSP balance)

    float* sq = sm + OFF_Q + q * Q_STRIDE;
    float* sq_img = sq + Q_IMG;
    float* sq_p1t = sq + Q_P1T;
    float* sq_p2  = sq + Q_P2;
    float* sq_fc1 = sq + Q_FC1;
    float* sq_fc2 = sq + Q_FC2;
    float* sq_log = sq + Q_LOG;

    for (int img = blockIdx.x * 4 + q; img < nimg; img += gridDim.x * 4) {

        // ---- load image (float4) ----
        {
            const float4* iv = reinterpret_cast<const float4*>(inputs + (size_t)img * 784);
            float4* ov = reinterpret_cast<float4*>(sq_img);
            for (int i = t; i < 196; i += 128) ov[i] = iv[i];
        }
        QBAR();

        // ---- conv1 (5x5x1->6) + relu + 2x2 maxpool, fused. 72 threads ----
        // thread = (py 0..11, xg 0..5); computes conv rows 2py,2py+1,
        // conv cols 4xg..4xg+3, all 6 channels (as 3 f32x2 channel pairs).
        if (rt < 72) {
            const int py = rt / 6, xg = rt % 6, x0 = 4 * xg;
            ull bp[3];
            #pragma unroll
            for (int cp = 0; cp < 3; cp++)
                bp[cp] = pack2(sm[OFF_B1 + 2 * cp], sm[OFF_B1 + 2 * cp + 1]);
            ull acc[2][4][3];
            #pragma unroll
            for (int dy = 0; dy < 2; dy++)
                #pragma unroll
                for (int dx = 0; dx < 4; dx++)
                    #pragma unroll
                    for (int cp = 0; cp < 3; cp++) acc[dy][dx][cp] = bp[cp];

            for (int r = 0; r < 6; r++) {
                const int iy = 2 * py + r;
                const float4* row = reinterpret_cast<const float4*>(sq_img + iy * 28 + x0);
                float4 v0 = row[0], v1 = row[1];
                ull ap[8];
                ap[0] = pack2(v0.x, v0.x); ap[1] = pack2(v0.y, v0.y);
                ap[2] = pack2(v0.z, v0.z); ap[3] = pack2(v0.w, v0.w);
                ap[4] = pack2(v1.x, v1.x); ap[5] = pack2(v1.y, v1.y);
                ap[6] = pack2(v1.z, v1.z); ap[7] = pack2(v1.w, v1.w);
                #pragma unroll
                for (int dy = 0; dy < 2; dy++) {
                    const int ky = r - dy;
                    if (ky < 0 || ky > 4) continue;
                    #pragma unroll
                    for (int kx = 0; kx < 5; kx++) {
                        const float* wp = sm + OFF_W1 + (ky * 5 + kx) * 6;
                        #pragma unroll
                        for (int cp = 0; cp < 3; cp++) {
                            ull w = lds64(wp + 2 * cp);
                            #pragma unroll
                            for (int dx = 0; dx < 4; dx++)
                                FMA2(acc[dy][dx][cp], ap[kx + dx], w, acc[dy][dx][cp]);
                        }
                    }
                }
            }
            // relu + pool + store (channel-major p1t)
            #pragma unroll
            for (int cp = 0; cp < 3; cp++) {
                #pragma unroll
                for (int dxp = 0; dxp < 2; dxp++) {
                    float2 a0 = unpack2(acc[0][2 * dxp][cp]);
                    float2 a1 = unpack2(acc[0][2 * dxp + 1][cp]);
                    float2 b0 = unpack2(acc[1][2 * dxp][cp]);
                    float2 b1 = unpack2(acc[1][2 * dxp + 1][cp]);
                    float m0 = fmaxf(fmaxf(a0.x, a1.x), fmaxf(b0.x, b1.x));
                    float m1 = fmaxf(fmaxf(a0.y, a1.y), fmaxf(b0.y, b1.y));
                    const int px = 2 * xg + dxp;
                    sq_p1t[(2 * cp)     * 144 + py * 12 + px] = fmaxf(m0, 0.0f);
                    sq_p1t[(2 * cp + 1) * 144 + py * 12 + px] = fmaxf(m1, 0.0f);
                }
            }
        }
        QBAR();

        // ---- conv2 (5x5x6->16) + relu + 2x2 maxpool, fused. 64 threads ----
        // thread = (py 0..3, xg 0..1, cg 0..7); conv rows 2py,2py+1,
        // conv cols 4xg..4xg+3, channels 2cg,2cg+1 (one f32x2 pair).
        if (rt < 64) {
            const int py = rt >> 4;
            const int xg = (rt >> 3) & 1;
            const int cg = rt & 7;
            const int x0 = 4 * xg;
            ull bp = lds64(sm + OFF_B2 + 2 * cg);
            ull acc[2][4];
            #pragma unroll
            for (int dy = 0; dy < 2; dy++)
                #pragma unroll
                for (int dx = 0; dx < 4; dx++) acc[dy][dx] = bp;

            for (int r = 0; r < 6; r++) {
                const int iy = 2 * py + r;
                for (int i = 0; i < 6; i++) {
                    const float4* row = reinterpret_cast<const float4*>(
                        sq_p1t + i * 144 + iy * 12 + x0);
                    float4 v0 = row[0], v1 = row[1];
                    ull ap[8];
                    ap[0] = pack2(v0.x, v0.x); ap[1] = pack2(v0.y, v0.y);
                    ap[2] = pack2(v0.z, v0.z); ap[3] = pack2(v0.w, v0.w);
                    ap[4] = pack2(v1.x, v1.x); ap[5] = pack2(v1.y, v1.y);
                    ap[6] = pack2(v1.z, v1.z); ap[7] = pack2(v1.w, v1.w);
                    #pragma unroll
                    for (int dy = 0; dy < 2; dy++) {
                        const int ky = r - dy;
                        if (ky < 0 || ky > 4) continue;
                        #pragma unroll
                        for (int kx = 0; kx < 5; kx++) {
                            ull w = lds64(sm + OFF_W2 + ((ky * 5 + kx) * 6 + i) * 16 + 2 * cg);
                            #pragma unroll
                            for (int dx = 0; dx < 4; dx++)
                                FMA2(acc[dy][dx], ap[kx + dx], w, acc[dy][dx]);
                        }
                    }
                }
            }
            // relu + pool + store (NHWC flat)
            #pragma unroll
            for (int dxp = 0; dxp < 2; dxp++) {
                float2 a0 = unpack2(acc[0][2 * dxp]);
                float2 a1 = unpack2(acc[0][2 * dxp + 1]);
                float2 b0 = unpack2(acc[1][2 * dxp]);
                float2 b1 = unpack2(acc[1][2 * dxp + 1]);
                float m0 = fmaxf(fmaxf(a0.x, a1.x), fmaxf(b0.x, b1.x));
                float m1 = fmaxf(fmaxf(a0.y, a1.y), fmaxf(b0.y, b1.y));
                const int px = 2 * xg + dxp;
                const int base = (py * 4 + px) * 16 + 2 * cg;
                sq_p2[base]     = fmaxf(m0, 0.0f);
                sq_p2[base + 1] = fmaxf(m1, 0.0f);
            }
        }
        QBAR();

        // ---- fc1: 256 -> 120, relu (transposed smem weights, f32x2) ----
        if (rt < 120) {
            ull acc0 = pack2(0.0f, 0.0f), acc1 = pack2(0.0f, 0.0f);
            const float* wr = sm + OFF_DW1T + rt * DW1_STR;
            #pragma unroll 8
            for (int k = 0; k < 256; k += 4) {
                ull a0 = lds64(sq_p2 + k), a1 = lds64(sq_p2 + k + 2);
                ull w0 = lds64(wr + k),    w1 = lds64(wr + k + 2);
                FMA2(acc0, a0, w0, acc0);
                FMA2(acc1, a1, w1, acc1);
            }
            float2 s0 = unpack2(acc0), s1 = unpack2(acc1);
            float v = s0.x + s0.y + s1.x + s1.y + sm[OFF_DB1 + rt];
            sq_fc1[rt] = fmaxf(v, 0.0f);
        }
        QBAR();

        // ---- fc2: 120 -> 84, relu ----
        if (rt < 84) {
            ull acc0 = pack2(0.0f, 0.0f), acc1 = pack2(0.0f, 0.0f);
            const float* wr = sm + OFF_DW2T + rt * DW2_STR;
            #pragma unroll 6
            for (int k = 0; k < 120; k += 4) {
                ull a0 = lds64(sq_fc1 + k), a1 = lds64(sq_fc1 + k + 2);
                ull w0 = lds64(wr + k),     w1 = lds64(wr + k + 2);
                FMA2(acc0, a0, w0, acc0);
                FMA2(acc1, a1, w1, acc1);
            }
            float2 s0 = unpack2(acc0), s1 = unpack2(acc1);
            float v = s0.x + s0.y + s1.x + s1.y + sm[OFF_DB2 + rt];
            sq_fc2[rt] = fmaxf(v, 0.0f);
        }
        QBAR();

        // ---- fc3: 84 -> 10 ----
        if (rt < 10) {
            float acc = sm[OFF_DB3 + rt];
            #pragma unroll 4
            for (int k = 0; k < 84; k++)
                acc = fmaf(sq_fc2[k], sm[OFF_DW3 + k * 10 + rt], acc);
            sq_log[rt] = acc;
        }
        QBAR();

        // ---- softmax -> scratch ----
        if (rt == 0) {
            float mx = sq_log[0];
            #pragma unroll
            for (int j = 1; j < 10; j++) mx = fmaxf(mx, sq_log[j]);
            float e[10], s = 0.0f;
            #pragma unroll
            for (int j = 0; j < 10; j++) { e[j] = __expf(sq_log[j] - mx); s += e[j]; }
            float inv = 1.0f / s;
            float* po = g_probs + (size_t)img * 10;
            #pragma unroll
            for (int j = 0; j < 10; j++) po[j] = e[j] * inv;
        }
        QBAR();
    }
}

// ---------------------------------------------------------------------------
// Kernel 2: Luhn DP. One thread per batch element.
// ---------------------------------------------------------------------------
__global__ void luhn_kernel(float* __restrict__ out, int B, int n)
{
    int b = blockIdx.x * blockDim.x + threadIdx.x;
    if (b >= B) return;

    const int LUHN[10] = {0, 5, 1, 6, 2, 7, 3, 8, 4, 9};
    const float* p = g_probs + (size_t)b * n * 10;
    const int m = n - 1;

    float cur[10];
    {
        const float* d = p + 10;
        bool perm = ((0 & 1) == (m & 1));
        #pragma unroll
        for (int j = 0; j < 10; j++) cur[j] = perm ? d[LUHN[j]] : d[j];
    }
    for (int i = 1; i < m; i++) {
        const float* d = p + (size_t)(i + 1) * 10;
        bool perm = ((i & 1) == (m & 1));
        float dd[10];
        #pragma unroll
        for (int j = 0; j < 10; j++) dd[j] = perm ? d[LUHN[j]] : d[j];
        float nxt[10];
        #pragma unroll
        for (int s = 0; s < 10; s++) nxt[s] = 0.0f;
        #pragma unroll
        for (int a = 0; a < 10; a++) {
            #pragma unroll
            for (int qd = 0; qd < 10; qd++) {
                nxt[(a + qd) % 10] = fmaf(cur[a], dd[qd], nxt[(a + qd) % 10]);
            }
        }
        #pragma unroll
        for (int s = 0; s < 10; s++) cur[s] = nxt[s];
    }
    const float* cd = p;
    float t10 = 0.0f;
    #pragma unroll
    for (int a = 1; a < 10; a++) t10 = fmaf(cd[a], cur[10 - a], t10);
    out[b] = logf(t10);
}

// ---------------------------------------------------------------------------
extern "C" void kernel_launch(void* const* d_in, const int* in_sizes, int n_in,
                              void* d_out, int out_size)
{
    const float* inputs = (const float*)d_in[0];
    const float* cw1    = (const float*)d_in[1];
    const float* cb1    = (const float*)d_in[2];
    const float* cw2    = (const float*)d_in[3];
    const float* cb2    = (const float*)d_in[4];
    const float* dw1    = (const float*)d_in[5];
    const float* db1    = (const float*)d_in[6];
    const float* dw2    = (const float*)d_in[7];
    const float* db2    = (const float*)d_in[8];
    const float* dw3    = (const float*)d_in[9];
    const float* db3    = (const float*)d_in[10];
    float* out = (float*)d_out;

    const int B = out_size;                      // 1024
    const int n = in_sizes[0] / (B * 784);       // 16
    const int nimg = B * n;

    const size_t smem_bytes = SMEM_FLOATS * sizeof(float);  // 213,408 B
    cudaFuncSetAttribute(cnn_kernel, cudaFuncAttributeMaxDynamicSharedMemorySize,
                         (int)smem_bytes);

    cnn_kernel<<<148, 512, smem_bytes>>>(inputs, cw1, cb1, cw2, cb2,
                                         dw1, db1, dw2, db2, dw3, db3, nimg);
    luhn_kernel<<<(B + 127) / 128, 128>>>(out, B, n);
}

// round 3
// speedup vs baseline: 2.1933x; 1.0066x over previous
#include <cuda_runtime.h>
#include <math.h>

typedef unsigned long long ull;

// ---------------------------------------------------------------------------
// packed fp32x2 helpers (Blackwell FFMA2)
// ---------------------------------------------------------------------------
#define FMA2(d, a, b, c) \
    asm("fma.rn.f32x2 %0, %1, %2, %3;" : "=l"(d) : "l"(a), "l"(b), "l"(c))

static __device__ __forceinline__ ull pack2(float lo, float hi) {
    ull r; asm("mov.b64 %0, {%1, %2};" : "=l"(r) : "f"(lo), "f"(hi)); return r;
}
static __device__ __forceinline__ float2 unpack2(ull v) {
    float2 r; asm("mov.b64 {%0, %1}, %2;" : "=f"(r.x), "=f"(r.y) : "l"(v)); return r;
}
static __device__ __forceinline__ ull lds64(const float* p) {
    return *reinterpret_cast<const ull*>(p);
}

// Scratch: per-image softmax probabilities (1024 batches * 16 digits * 10)
__device__ float g_probs[1024 * 16 * 10];

// ---------------------------------------------------------------------------
// shared memory layout (float offsets)
// ---------------------------------------------------------------------------
#define OFF_DW1T  0        // [120][258]  transposed dw1, padded
#define DW1_STR   258
#define OFF_DW2T  30960    // [84][122]   transposed dw2, padded
#define DW2_STR   122
#define OFF_DW3   41208    // 840
#define OFF_W1    42048    // 150 (+2 pad)
#define OFF_W2    42200    // 2400
#define OFF_B1    44600    // 6 (+2)
#define OFF_B2    44608    // 16
#define OFF_DB1   44624    // 120
#define OFF_DB2   44744    // 84
#define OFF_DB3   44828    // 10 (+2)
#define OFF_IMG   44840    // [4][784]
#define OFF_P1T   47976    // [4][6][12][24]  (pooled conv1, dup pairs)
#define P1_IMG_STR 1728
#define OFF_P2    54888    // [4][264]  (256 used, padded to 264)
#define P2_STR    264
#define OFF_FC1   55944    // [4][120]
#define OFF_FC2   56424    // [4][84]
#define OFF_LOG   56760    // [4][12]
#define SMEM_FLOATS 56808  // = 227,232 bytes

// ---------------------------------------------------------------------------
// Kernel 1: persistent fused LeNet. 148 CTAs x 512 threads, CTA-wide phases
// over batches of 4 images.
// ---------------------------------------------------------------------------
__global__ void __launch_bounds__(512, 1) cnn_kernel(
    const float* __restrict__ inputs,
    const float* __restrict__ cw1, const float* __restrict__ cb1,
    const float* __restrict__ cw2, const float* __restrict__ cb2,
    const float* __restrict__ dw1, const float* __restrict__ db1,
    const float* __restrict__ dw2, const float* __restrict__ db2,
    const float* __restrict__ dw3, const float* __restrict__ db3,
    int nimg)
{
    extern __shared__ float sm[];
    const int tid = threadIdx.x;

    // ---- one-time weight staging ----
    for (int idx = tid; idx < 256 * 120; idx += 512) {
        int k = idx / 120, j = idx % 120;               // dw1[k][j]
        sm[OFF_DW1T + j * DW1_STR + k] = dw1[idx];
    }
    for (int idx = tid; idx < 120 * 84; idx += 512) {
        int k = idx / 84, j = idx % 84;                 // dw2[k][j]
        sm[OFF_DW2T + j * DW2_STR + k] = dw2[idx];
    }
    for (int idx = tid; idx < 840;  idx += 512) sm[OFF_DW3 + idx] = dw3[idx];
    for (int idx = tid; idx < 150;  idx += 512) sm[OFF_W1  + idx] = cw1[idx];
    for (int idx = tid; idx < 2400; idx += 512) sm[OFF_W2  + idx] = cw2[idx];
    if (tid < 6)   sm[OFF_B1  + tid] = cb1[tid];
    if (tid < 16)  sm[OFF_B2  + tid] = cb2[tid];
    if (tid < 120) sm[OFF_DB1 + tid] = db1[tid];
    if (tid < 84)  sm[OFF_DB2 + tid] = db2[tid];
    if (tid < 10)  sm[OFF_DB3 + tid] = db3[tid];

    // ---- prologue: load first batch of 4 images ----
    {
        const int b0 = blockIdx.x * 4;
        if (b0 < nimg) {
            const float4* iv = reinterpret_cast<const float4*>(inputs + (size_t)b0 * 784);
            float4* ov = reinterpret_cast<float4*>(sm + OFF_IMG);
            for (int i = tid; i < 784; i += 512) ov[i] = iv[i];
        }
    }
    __syncthreads();

    for (int base = blockIdx.x * 4; base < nimg; base += gridDim.x * 4) {

        // =========== conv1 (5x5->6) + relu + pool. 288 threads ===========
        if (tid < 288) {
            const int img = tid / 72;
            const int r72 = tid % 72;
            const int py = r72 / 6, xg = r72 % 6, x0 = 4 * xg;
            const float* s_img = sm + OFF_IMG + img * 784;
            float* s_p1 = sm + OFF_P1T + img * P1_IMG_STR;

            ull bp[3];
            #pragma unroll
            for (int cp = 0; cp < 3; cp++)
                bp[cp] = pack2(sm[OFF_B1 + 2 * cp], sm[OFF_B1 + 2 * cp + 1]);
            ull acc[2][4][3];
            #pragma unroll
            for (int dy = 0; dy < 2; dy++)
                #pragma unroll
                for (int dx = 0; dx < 4; dx++)
                    #pragma unroll
                    for (int cp = 0; cp < 3; cp++) acc[dy][dx][cp] = bp[cp];

            for (int r = 0; r < 6; r++) {
                const int iy = 2 * py + r;
                const float4* row = reinterpret_cast<const float4*>(s_img + iy * 28 + x0);
                float4 v0 = row[0], v1 = row[1];
                ull ap[8];
                ap[0] = pack2(v0.x, v0.x); ap[1] = pack2(v0.y, v0.y);
                ap[2] = pack2(v0.z, v0.z); ap[3] = pack2(v0.w, v0.w);
                ap[4] = pack2(v1.x, v1.x); ap[5] = pack2(v1.y, v1.y);
                ap[6] = pack2(v1.z, v1.z); ap[7] = pack2(v1.w, v1.w);
                #pragma unroll
                for (int dy = 0; dy < 2; dy++) {
                    const int ky = r - dy;
                    if (ky < 0 || ky > 4) continue;
                    #pragma unroll
                    for (int kx = 0; kx < 5; kx++) {
                        const float* wp = sm + OFF_W1 + (ky * 5 + kx) * 6;
                        #pragma unroll
                        for (int cp = 0; cp < 3; cp++) {
                            ull w = lds64(wp + 2 * cp);
                            #pragma unroll
                            for (int dx = 0; dx < 4; dx++)
                                FMA2(acc[dy][dx][cp], ap[kx + dx], w, acc[dy][dx][cp]);
                        }
                    }
                }
            }
            #pragma unroll
            for (int cp = 0; cp < 3; cp++) {
                #pragma unroll
                for (int dxp = 0; dxp < 2; dxp++) {
                    float2 a0 = unpack2(acc[0][2 * dxp][cp]);
                    float2 a1 = unpack2(acc[0][2 * dxp + 1][cp]);
                    float2 b0 = unpack2(acc[1][2 * dxp][cp]);
                    float2 b1 = unpack2(acc[1][2 * dxp + 1][cp]);
                    float m0 = fmaxf(fmaxf(fmaxf(a0.x, a1.x), fmaxf(b0.x, b1.x)), 0.0f);
                    float m1 = fmaxf(fmaxf(fmaxf(a0.y, a1.y), fmaxf(b0.y, b1.y)), 0.0f);
                    const int px = 2 * xg + dxp;
                    *reinterpret_cast<ull*>(s_p1 + ((2 * cp)     * 12 + py) * 24 + 2 * px) = pack2(m0, m0);
                    *reinterpret_cast<ull*>(s_p1 + ((2 * cp + 1) * 12 + py) * 24 + 2 * px) = pack2(m1, m1);
                }
            }
        }
        __syncthreads();

        // =========== conv2 (5x5x6->16) + relu + pool. 256 threads =========
        if (tid < 256) {
            const int img = tid >> 6;
            const int u   = tid & 63;
            const int py = u >> 4, xg = (u >> 3) & 1, cg = u & 7;
            const int x0 = 4 * xg;
            const float* s_p1 = sm + OFF_P1T + img * P1_IMG_STR;

            ull bp = lds64(sm + OFF_B2 + 2 * cg);
            ull acc[2][4];
            #pragma unroll
            for (int dy = 0; dy < 2; dy++)
                #pragma unroll
                for (int dx = 0; dx < 4; dx++) acc[dy][dx] = bp;

            for (int r = 0; r < 6; r++) {
                const int iy = 2 * py + r;
                for (int i = 0; i < 6; i++) {
                    const float* row = s_p1 + (i * 12 + iy) * 24 + 2 * x0;
                    ull ap[8];
                    #pragma unroll
                    for (int j = 0; j < 8; j++) ap[j] = lds64(row + 2 * j);
                    #pragma unroll
                    for (int dy = 0; dy < 2; dy++) {
                        const int ky = r - dy;
                        if (ky < 0 || ky > 4) continue;
                        #pragma unroll
                        for (int kx = 0; kx < 5; kx++) {
                            ull w = lds64(sm + OFF_W2 + ((ky * 5 + kx) * 6 + i) * 16 + 2 * cg);
                            #pragma unroll
                            for (int dx = 0; dx < 4; dx++)
                                FMA2(acc[dy][dx], ap[kx + dx], w, acc[dy][dx]);
                        }
                    }
                }
            }
            float* s_p2 = sm + OFF_P2 + img * P2_STR;
            #pragma unroll
            for (int dxp = 0; dxp < 2; dxp++) {
                float2 a0 = unpack2(acc[0][2 * dxp]);
                float2 a1 = unpack2(acc[0][2 * dxp + 1]);
                float2 b0 = unpack2(acc[1][2 * dxp]);
                float2 b1 = unpack2(acc[1][2 * dxp + 1]);
                float m0 = fmaxf(fmaxf(fmaxf(a0.x, a1.x), fmaxf(b0.x, b1.x)), 0.0f);
                float m1 = fmaxf(fmaxf(fmaxf(a0.y, a1.y), fmaxf(b0.y, b1.y)), 0.0f);
                const int px = 2 * xg + dxp;
                *reinterpret_cast<ull*>(s_p2 + (py * 4 + px) * 16 + 2 * cg) = pack2(m0, m1);
            }
        } else {
            // prefetch next batch of 4 images (img smem is dead after conv1)
            const int nb = base + gridDim.x * 4;
            if (nb < nimg) {
                const float4* iv = reinterpret_cast<const float4*>(inputs + (size_t)nb * 784);
                float4* ov = reinterpret_cast<float4*>(sm + OFF_IMG);
                for (int i = tid - 256; i < 784; i += 256) ov[i] = iv[i];
            }
        }
        __syncthreads();

        // =========== fc1: 256 -> 120, relu. 480 threads (j*4+img) =========
        if (tid < 480) {
            const int j = tid >> 2, img = tid & 3;
            const float* act = sm + OFF_P2 + img * P2_STR;
            const float* wr  = sm + OFF_DW1T + j * DW1_STR;
            ull acc0 = pack2(0.0f, 0.0f), acc1 = pack2(0.0f, 0.0f);
            #pragma unroll 8
            for (int k = 0; k < 256; k += 4) {
                ull a0 = lds64(act + k), a1 = lds64(act + k + 2);
                ull w0 = lds64(wr + k),  w1 = lds64(wr + k + 2);
                FMA2(acc0, a0, w0, acc0);
                FMA2(acc1, a1, w1, acc1);
            }
            float2 s0 = unpack2(acc0), s1 = unpack2(acc1);
            float v = s0.x + s0.y + s1.x + s1.y + sm[OFF_DB1 + j];
            sm[OFF_FC1 + img * 120 + j] = fmaxf(v, 0.0f);
        }
        __syncthreads();

        // =========== fc2: 120 -> 84, relu. 336 threads ===========
        if (tid < 336) {
            const int j = tid >> 2, img = tid & 3;
            const float* act = sm + OFF_FC1 + img * 120;
            const float* wr  = sm + OFF_DW2T + j * DW2_STR;
            ull acc0 = pack2(0.0f, 0.0f), acc1 = pack2(0.0f, 0.0f);
            #pragma unroll 6
            for (int k = 0; k < 120; k += 4) {
                ull a0 = lds64(act + k), a1 = lds64(act + k + 2);
                ull w0 = lds64(wr + k),  w1 = lds64(wr + k + 2);
                FMA2(acc0, a0, w0, acc0);
                FMA2(acc1, a1, w1, acc1);
            }
            float2 s0 = unpack2(acc0), s1 = unpack2(acc1);
            float v = s0.x + s0.y + s1.x + s1.y + sm[OFF_DB2 + j];
            sm[OFF_FC2 + img * 84 + j] = fmaxf(v, 0.0f);
        }
        __syncthreads();

        // =========== fc3: 84 -> 10. 40 threads ===========
        if (tid < 40) {
            const int j = tid >> 2, img = tid & 3;
            const float* act = sm + OFF_FC2 + img * 84;
            float acc = sm[OFF_DB3 + j];
            #pragma unroll 4
            for (int k = 0; k < 84; k++)
                acc = fmaf(act[k], sm[OFF_DW3 + k * 10 + j], acc);
            sm[OFF_LOG + img * 12 + j] = acc;
        }
        __syncthreads();

        // =========== softmax -> scratch. 4 threads ===========
        if (tid < 4) {
            const float* lg = sm + OFF_LOG + tid * 12;
            float mx = lg[0];
            #pragma unroll
            for (int j = 1; j < 10; j++) mx = fmaxf(mx, lg[j]);
            float e[10], s = 0.0f;
            #pragma unroll
            for (int j = 0; j < 10; j++) { e[j] = __expf(lg[j] - mx); s += e[j]; }
            float inv = 1.0f / s;
            float* po = g_probs + (size_t)(base + tid) * 10;
            #pragma unroll
            for (int j = 0; j < 10; j++) po[j] = e[j] * inv;
        }
        __syncthreads();
    }
}

// ---------------------------------------------------------------------------
// Kernel 2: Luhn DP.
// ---------------------------------------------------------------------------
template <int N>
__device__ __forceinline__ float luhn_eval(const float* __restrict__ p)
{
    const int LUHN[10] = {0, 5, 1, 6, 2, 7, 3, 8, 4, 9};
    float4 v[(N * 10) / 4];
    const float4* pv = reinterpret_cast<const float4*>(p);
    #pragma unroll
    for (int i = 0; i < (N * 10) / 4; i++) v[i] = pv[i];
    float d[N * 10];
    #pragma unroll
    for (int i = 0; i < (N * 10) / 4; i++) {
        d[4 * i] = v[i].x; d[4 * i + 1] = v[i].y;
        d[4 * i + 2] = v[i].z; d[4 * i + 3] = v[i].w;
    }
    const int m = N - 1;
    float cur[10];
    #pragma unroll
    for (int j = 0; j < 10; j++)
        cur[j] = ((0 % 2) == (m % 2)) ? d[10 + LUHN[j]] : d[10 + j];
    #pragma unroll
    for (int i = 1; i < m; i++) {
        float dd[10];
        #pragma unroll
        for (int j = 0; j < 10; j++)
            dd[j] = ((i % 2) == (m % 2)) ? d[(i + 1) * 10 + LUHN[j]] : d[(i + 1) * 10 + j];
        float nxt[10];
        #pragma unroll
        for (int s = 0; s < 10; s++) nxt[s] = 0.0f;
        #pragma unroll
        for (int a = 0; a < 10; a++)
            #pragma unroll
            for (int q = 0; q < 10; q++)
                nxt[(a + q) % 10] = fmaf(cur[a], dd[q], nxt[(a + q) % 10]);
        #pragma unroll
        for (int s = 0; s < 10; s++) cur[s] = nxt[s];
    }
    float t10 = 0.0f;
    #pragma unroll
    for (int a = 1; a < 10; a++) t10 = fmaf(d[a], cur[10 - a], t10);
    return logf(t10);
}

__device__ float luhn_generic(const float* __restrict__ p, int n)
{
    const int LUHN[10] = {0, 5, 1, 6, 2, 7, 3, 8, 4, 9};
    const int m = n - 1;
    float cur[10];
    {
        const float* d = p + 10;
        bool perm = ((0 & 1) == (m & 1));
        #pragma unroll
        for (int j = 0; j < 10; j++) cur[j] = perm ? d[LUHN[j]] : d[j];
    }
    for (int i = 1; i < m; i++) {
        const float* d = p + (size_t)(i + 1) * 10;
        bool perm = ((i & 1) == (m & 1));
        float dd[10];
        #pragma unroll
        for (int j = 0; j < 10; j++) dd[j] = perm ? d[LUHN[j]] : d[j];
        float nxt[10];
        #pragma unroll
        for (int s = 0; s < 10; s++) nxt[s] = 0.0f;
        #pragma unroll
        for (int a = 0; a < 10; a++)
            #pragma unroll
            for (int q = 0; q < 10; q++)
                nxt[(a + q) % 10] = fmaf(cur[a], dd[q], nxt[(a + q) % 10]);
        #pragma unroll
        for (int s = 0; s < 10; s++) cur[s] = nxt[s];
    }
    float t10 = 0.0f;
    #pragma unroll
    for (int a = 1; a < 10; a++) t10 = fmaf(p[a], cur[10 - a], t10);
    return logf(t10);
}

__global__ void luhn_kernel(float* __restrict__ out, int B, int n)
{
    int b = blockIdx.x * blockDim.x + threadIdx.x;
    if (b >= B) return;
    const float* p = g_probs + (size_t)b * n * 10;
    if (n == 16) out[b] = luhn_eval<16>(p);
    else         out[b] = luhn_generic(p, n);
}

// ---------------------------------------------------------------------------
extern "C" void kernel_launch(void* const* d_in, const int* in_sizes, int n_in,
                              void* d_out, int out_size)
{
    const float* inputs = (const float*)d_in[0];
    const float* cw1    = (const float*)d_in[1];
    const float* cb1    = (const float*)d_in[2];
    const float* cw2    = (const float*)d_in[3];
    const float* cb2    = (const float*)d_in[4];
    const float* dw1    = (const float*)d_in[5];
    const float* db1    = (const float*)d_in[6];
    const float* dw2    = (const float*)d_in[7];
    const float* db2    = (const float*)d_in[8];
    const float* dw3    = (const float*)d_in[9];
    const float* db3    = (const float*)d_in[10];
    float* out = (float*)d_out;

    const int B = out_size;                      // 1024
    const int n = in_sizes[0] / (B * 784);       // 16
    const int nimg = B * n;

    const size_t smem_bytes = SMEM_FLOATS * sizeof(float);  // 227,232 B
    cudaFuncSetAttribute(cnn_kernel, cudaFuncAttributeMaxDynamicSharedMemorySize,
                         (int)smem_bytes);

    cnn_kernel<<<148, 512, smem_bytes>>>(inputs, cw1, cb1, cw2, cb2,
                                         dw1, db1, dw2, db2, dw3, db3, nimg);
    luhn_kernel<<<(B + 15) / 16, 16>>>(out, B, n);
}